// round 12
// baseline (speedup 1.0000x reference)
#include <cuda_runtime.h>
#include <cuda_fp16.h>
#include <cstdint>

#define NEXP 8
#define NTOK 8192
#define H    2048
#define I2   4096
#define ID   2048
#define MAXTILES 136
#define PADSLOTS (MAXTILES*128)

// ---------------- static scratch ----------------
__device__ int    g_count[NEXP];
__device__ int    g_offset[NEXP];
__device__ int    g_ntiles;
__device__ int    g_tile_e[MAXTILES];
__device__ int    g_tok[NEXP*NTOK];
__device__ int    g_slot[NTOK*2];
__device__ float2 g_wv[NTOK];
__device__ __align__(16) __half g_xh [(size_t)PADSLOTS*H];
__device__ __align__(16) __half g_yh [(size_t)PADSLOTS*ID];
__device__ __align__(16) float  g_ob [(size_t)PADSLOTS*H];
__device__ __align__(16) __half g_w1h[(size_t)NEXP*I2*H];
__device__ __align__(16) __half g_w2h[(size_t)NEXP*H*ID];

// ---------------- small kernels ----------------
__global__ void k_init(){ if (threadIdx.x < NEXP) g_count[threadIdx.x] = 0; }

__global__ void k_gate(const float* __restrict__ x, const float* __restrict__ gw,
                       const float* __restrict__ gb){
    int warp = (blockIdx.x * blockDim.x + threadIdx.x) >> 5;
    int lane = threadIdx.x & 31;
    if (warp >= NTOK) return;
    const float* xr = x + (size_t)warp * H;
    float acc[NEXP];
#pragma unroll
    for (int e = 0; e < NEXP; e++) acc[e] = 0.f;
    for (int i = lane; i < H; i += 32){
        float xv = xr[i];
#pragma unroll
        for (int e = 0; e < NEXP; e++) acc[e] += xv * gw[e*H + i];
    }
#pragma unroll
    for (int e = 0; e < NEXP; e++)
#pragma unroll
        for (int o = 16; o > 0; o >>= 1) acc[e] += __shfl_xor_sync(0xffffffffu, acc[e], o);
    if (lane == 0){
        float lg[NEXP];
#pragma unroll
        for (int e = 0; e < NEXP; e++) lg[e] = acc[e] + gb[e];
        int b0 = 0;
#pragma unroll
        for (int e = 1; e < NEXP; e++) if (lg[e] > lg[b0]) b0 = e;
        int b1 = -1;
#pragma unroll
        for (int e = 0; e < NEXP; e++){ if (e == b0) continue; if (b1 < 0 || lg[e] > lg[b1]) b1 = e; }
        float e1 = expf(lg[b1] - lg[b0]);
        float inv = 1.f / (1.f + e1);
        g_wv[warp] = make_float2(inv, e1 * inv);
        int p0 = atomicAdd(&g_count[b0], 1); g_tok[b0*NTOK + p0] = warp*2 + 0;
        int p1 = atomicAdd(&g_count[b1], 1); g_tok[b1*NTOK + p1] = warp*2 + 1;
    }
}

__global__ void k_scan(){
    if (threadIdx.x == 0){
        int base = 0, nt = 0;
        for (int e = 0; e < NEXP; e++){
            g_offset[e] = base;
            int t = (g_count[e] + 127) >> 7;
            for (int i = 0; i < t; i++) g_tile_e[nt++] = e;
            base += t * 128;
        }
        g_ntiles = nt;
    }
}

// gather x rows -> fp16 compacted
__global__ void k_gather(const float* __restrict__ x){
    int e = blockIdx.x, pos0 = blockIdx.y * 8, cnt = g_count[e];
    if (pos0 >= cnt) return;
    int off = g_offset[e];
    for (int r = 0; r < 8; r++){
        int pos = pos0 + r; if (pos >= cnt) break;
        int code = g_tok[e*NTOK + pos], t = code >> 1, slot = off + pos;
        if (threadIdx.x == 0) g_slot[code] = slot;
        const float4* src = (const float4*)(x + (size_t)t * H);
        uint4* dst = (uint4*)(g_xh + (size_t)slot * H);
        for (int i = threadIdx.x; i < H/8; i += blockDim.x){
            float4 v0 = src[2*i], v1 = src[2*i+1];
            __half2 h0 = __floats2half2_rn(v0.x, v0.y), h1 = __floats2half2_rn(v0.z, v0.w);
            __half2 h2 = __floats2half2_rn(v1.x, v1.y), h3 = __floats2half2_rn(v1.z, v1.w);
            uint4 u;
            u.x = *(uint32_t*)&h0; u.y = *(uint32_t*)&h1;
            u.z = *(uint32_t*)&h2; u.w = *(uint32_t*)&h3;
            dst[i] = u;
        }
    }
}

// fp32 weights -> fp16 (row-major, coalesced)
__global__ void k_cvt(const float4* __restrict__ W, uint4* __restrict__ O){
    size_t i = (size_t)blockIdx.x * blockDim.x + threadIdx.x;
    float4 v0 = W[2*i], v1 = W[2*i+1];
    __half2 h0 = __floats2half2_rn(v0.x, v0.y), h1 = __floats2half2_rn(v0.z, v0.w);
    __half2 h2 = __floats2half2_rn(v1.x, v1.y), h3 = __floats2half2_rn(v1.z, v1.w);
    uint4 u;
    u.x = *(uint32_t*)&h0; u.y = *(uint32_t*)&h1;
    u.z = *(uint32_t*)&h2; u.w = *(uint32_t*)&h3;
    O[i] = u;
}

// ---------------- HFMA2 SIMT GEMM (regs-safe, double-buffered) ----------------
// C(128x128) = A(128x2048) * W(128x2048)^T, fp16 ops, fp16 chunk accum (C=8 k-steps),
// chunk sums spilled to fp32. 512 threads, microtile 4 rows x 8 cols (4 half2 pairs).
// Accumulator pair (cols 2j,2j+1) = SwiGLU (glu,lin) pair.
template<bool SWIGLU>
__global__ __launch_bounds__(512, 1) void k_hgemm(const __half* __restrict__ Wh,
                                                  const float* __restrict__ Bb){
    int tile = blockIdx.x;
    if (tile >= g_ntiles) return;
    const int Nr = SWIGLU ? I2 : H;
    int e     = g_tile_e[tile];
    int sbase = tile * 128;
    int n0    = blockIdx.y * 128;
    const __half* A = (SWIGLU ? g_xh : g_yh) + (size_t)sbase * H;
    const __half* W = Wh + ((size_t)e * Nr + n0) * H;
    const float* bs = Bb + (size_t)e * Nr + n0;

    // double-buffered smem
    __shared__ __align__(16) __half2 Asd[2][128][16];   // [buf][row][k] duplicated (a,a)
    __shared__ __align__(16) __half  Bsh[2][16][136];   // [buf][k][ncol], padded row

    int tid = threadIdx.x;
    int tm = (tid >> 4) << 2;          // 4-row group (0,4,...,124)
    int tn = (tid & 15) << 3;          // 8-col group (0,8,...,120)
    int prow = tid >> 2, pkg = tid & 3;  // producer: row 0..127, k-subgroup of 4
    const __half* Ap = A + (size_t)prow * H + pkg * 4;
    const __half* Bp = W + (size_t)prow * H + pkg * 4;

    __half2 hacc[4][4];
    float2  facc[4][4];
#pragma unroll
    for (int i = 0; i < 4; i++)
#pragma unroll
        for (int j = 0; j < 4; j++) facc[i][j] = make_float2(0.f, 0.f);

    uint2 pa = *(const uint2*)Ap;
    uint2 pb = *(const uint2*)Bp;

    for (int kt = 0; kt < 128; kt++){
        int buf = kt & 1;
        // producer: store prefetched data for THIS kt into buf
        {
            uint32_t d0 = __byte_perm(pa.x, pa.x, 0x1010);
            uint32_t d1 = __byte_perm(pa.x, pa.x, 0x3232);
            uint32_t d2 = __byte_perm(pa.y, pa.y, 0x1010);
            uint32_t d3 = __byte_perm(pa.y, pa.y, 0x3232);
            uint4 du; du.x = d0; du.y = d1; du.z = d2; du.w = d3;
            *(uint4*)&Asd[buf][prow][pkg*4] = du;       // STS.128, conflict-free
            union { uint2 u; __half h[4]; } bu; bu.u = pb;
#pragma unroll
            for (int j = 0; j < 4; j++) Bsh[buf][pkg*4 + j][prow] = bu.h[j];
        }
        // prefetch next kt from gmem (latency hidden by compute below)
        if (kt + 1 < 128){
            pa = *(const uint2*)(Ap + (kt + 1) * 16);
            pb = *(const uint2*)(Bp + (kt + 1) * 16);
        }
        __syncthreads();   // buf[kt&1] ready; also guarantees buf[(kt-1)&1] consumers done

        // consume 16 k-steps as 8 pairs
#pragma unroll
        for (int kp = 0; kp < 8; kp++){
            __half2 a0[4], a1[4];
#pragma unroll
            for (int r = 0; r < 4; r++){
                uint2 t = *(const uint2*)&Asd[buf][tm + r][2*kp];   // LDS.64, broadcast
                a0[r] = *(__half2*)&t.x;
                a1[r] = *(__half2*)&t.y;
            }
            __half2 b0[4], b1[4];
            *(uint4*)b0 = *(const uint4*)&Bsh[buf][2*kp][tn];
            *(uint4*)b1 = *(const uint4*)&Bsh[buf][2*kp + 1][tn];
            if ((kp & 3) == 0){
#pragma unroll
                for (int i = 0; i < 4; i++)
#pragma unroll
                    for (int j = 0; j < 4; j++) hacc[i][j] = __hmul2(a0[i], b0[j]);
            } else {
#pragma unroll
                for (int i = 0; i < 4; i++)
#pragma unroll
                    for (int j = 0; j < 4; j++) hacc[i][j] = __hfma2(a0[i], b0[j], hacc[i][j]);
            }
#pragma unroll
            for (int i = 0; i < 4; i++)
#pragma unroll
                for (int j = 0; j < 4; j++) hacc[i][j] = __hfma2(a1[i], b1[j], hacc[i][j]);
            if ((kp & 3) == 3){
#pragma unroll
                for (int i = 0; i < 4; i++)
#pragma unroll
                    for (int j = 0; j < 4; j++){
                        float2 f = __half22float2(hacc[i][j]);
                        facc[i][j].x += f.x; facc[i][j].y += f.y;
                    }
            }
        }
    }

    if (SWIGLU){
#pragma unroll
        for (int i = 0; i < 4; i++){
            int slot = sbase + tm + i;
            __half hv[4];
#pragma unroll
            for (int j = 0; j < 4; j++){
                float glu = facc[i][j].x + bs[tn + 2*j];
                float lin = facc[i][j].y + bs[tn + 2*j + 1];
                float s = 1.f / (1.f + expf(-1.702f * glu));
                hv[j] = __float2half_rn(glu * s * (lin + 1.f));
            }
            *(uint2*)(g_yh + (size_t)slot * ID + ((n0 + tn) >> 1)) = *(uint2*)hv;
        }
    } else {
#pragma unroll
        for (int i = 0; i < 4; i++){
            int slot = sbase + tm + i;
            float* orow = g_ob + (size_t)slot * H + n0 + tn;
            float4 v0, v1;
            v0.x = facc[i][0].x + bs[tn + 0]; v0.y = facc[i][0].y + bs[tn + 1];
            v0.z = facc[i][1].x + bs[tn + 2]; v0.w = facc[i][1].y + bs[tn + 3];
            v1.x = facc[i][2].x + bs[tn + 4]; v1.y = facc[i][2].y + bs[tn + 5];
            v1.z = facc[i][3].x + bs[tn + 6]; v1.w = facc[i][3].y + bs[tn + 7];
            *(float4*)orow = v0;
            *(float4*)(orow + 4) = v1;
        }
    }
}

__global__ void k_comb(float* __restrict__ out){
    int gid = blockIdx.x * blockDim.x + threadIdx.x;
    if (gid >= NTOK * (H/4)) return;
    int t = gid / (H/4), c4 = gid % (H/4);
    int s0 = g_slot[2*t], s1 = g_slot[2*t + 1];
    float2 w = g_wv[t];
    float4 a = *((const float4*)(g_ob + (size_t)s0 * H) + c4);
    float4 b = *((const float4*)(g_ob + (size_t)s1 * H) + c4);
    float4 r;
    r.x = w.x*a.x + w.y*b.x; r.y = w.x*a.y + w.y*b.y;
    r.z = w.x*a.z + w.y*b.z; r.w = w.x*a.w + w.y*b.w;
    *((float4*)out + gid) = r;
}

// ---------------- launcher ----------------
extern "C" void kernel_launch(void* const* d_in, const int* in_sizes, int n_in,
                              void* d_out, int out_size){
    const float* x  = (const float*)d_in[0];
    const float* gw = (const float*)d_in[1];
    const float* gb = (const float*)d_in[2];
    const float* w1 = (const float*)d_in[3];
    const float* b1 = (const float*)d_in[4];
    const float* w2 = (const float*)d_in[5];
    const float* b2 = (const float*)d_in[6];
    float* out = (float*)d_out;

    k_init<<<1, 32>>>();
    k_gate<<<NTOK/8, 256>>>(x, gw, gb);
    k_scan<<<1, 32>>>();
    k_gather<<<dim3(NEXP, NTOK/8), 256>>>(x);
    k_cvt<<<32768, 256>>>((const float4*)w1, (uint4*)g_w1h);
    k_cvt<<<16384, 256>>>((const float4*)w2, (uint4*)g_w2h);
    k_hgemm<true ><<<dim3(MAXTILES, I2/128), 512>>>(g_w1h, b1);
    k_hgemm<false><<<dim3(MAXTILES, H /128), 512>>>(g_w2h, b2);
    k_comb<<<(NTOK*(H/4) + 255)/256, 256>>>(out);
}

// round 14
// speedup vs baseline: 1.9145x; 1.9145x over previous
#include <cuda_runtime.h>
#include <cstdint>

#define NEXP 8
#define NTOK 8192
#define H    2048
#define I2   4096
#define ID   2048
#define MAXTILES 136
#define PADSLOTS (MAXTILES*128)

typedef unsigned long long u64t;

// ---------------- static scratch ----------------
__device__ int    g_count[NEXP];
__device__ int    g_offset[NEXP];
__device__ int    g_ntiles;
__device__ int    g_tile_e[MAXTILES];
__device__ int    g_tok[NEXP*NTOK];
__device__ int    g_slot[NTOK*2];
__device__ float2 g_wv[NTOK];
__device__ __align__(16) float g_xg[(size_t)PADSLOTS*H];
__device__ __align__(16) float g_y [(size_t)PADSLOTS*ID];
__device__ __align__(16) float g_ob[(size_t)PADSLOTS*H];

// ---------------- f32x2 helpers ----------------
__device__ __forceinline__ void unpack2(u64t v, float& lo, float& hi){
    asm("mov.b64 {%0, %1}, %2;" : "=f"(lo), "=f"(hi) : "l"(v));
}
__device__ __forceinline__ void fma2(u64t& c, u64t a, u64t b){
    asm("fma.rn.f32x2 %0, %1, %2, %0;" : "+l"(c) : "l"(a), "l"(b));
}

// ---------------- small kernels ----------------
__global__ void k_init(){ if (threadIdx.x < NEXP) g_count[threadIdx.x] = 0; }

__global__ void k_gate(const float* __restrict__ x, const float* __restrict__ gw,
                       const float* __restrict__ gb){
    int warp = (blockIdx.x * blockDim.x + threadIdx.x) >> 5;
    int lane = threadIdx.x & 31;
    if (warp >= NTOK) return;
    const float* xr = x + (size_t)warp * H;
    float acc[NEXP];
#pragma unroll
    for (int e = 0; e < NEXP; e++) acc[e] = 0.f;
    for (int i = lane; i < H; i += 32){
        float xv = xr[i];
#pragma unroll
        for (int e = 0; e < NEXP; e++) acc[e] += xv * gw[e*H + i];
    }
#pragma unroll
    for (int e = 0; e < NEXP; e++)
#pragma unroll
        for (int o = 16; o > 0; o >>= 1) acc[e] += __shfl_xor_sync(0xffffffffu, acc[e], o);
    if (lane == 0){
        float lg[NEXP];
#pragma unroll
        for (int e = 0; e < NEXP; e++) lg[e] = acc[e] + gb[e];
        int b0 = 0;
#pragma unroll
        for (int e = 1; e < NEXP; e++) if (lg[e] > lg[b0]) b0 = e;
        int b1 = -1;
#pragma unroll
        for (int e = 0; e < NEXP; e++){ if (e == b0) continue; if (b1 < 0 || lg[e] > lg[b1]) b1 = e; }
        float e1 = expf(lg[b1] - lg[b0]);
        float inv = 1.f / (1.f + e1);
        g_wv[warp] = make_float2(inv, e1 * inv);
        int p0 = atomicAdd(&g_count[b0], 1); g_tok[b0*NTOK + p0] = warp*2 + 0;
        int p1 = atomicAdd(&g_count[b1], 1); g_tok[b1*NTOK + p1] = warp*2 + 1;
    }
}

__global__ void k_scan(){
    if (threadIdx.x == 0){
        int base = 0, nt = 0;
        for (int e = 0; e < NEXP; e++){
            g_offset[e] = base;
            int t = (g_count[e] + 127) >> 7;
            for (int i = 0; i < t; i++) g_tile_e[nt++] = e;
            base += t * 128;
        }
        g_ntiles = nt;
    }
}

__global__ void k_gather(const float* __restrict__ x){
    int e = blockIdx.x, pos0 = blockIdx.y * 8, cnt = g_count[e];
    if (pos0 >= cnt) return;
    int off = g_offset[e];
    for (int r = 0; r < 8; r++){
        int pos = pos0 + r; if (pos >= cnt) break;
        int code = g_tok[e*NTOK + pos], t = code >> 1, slot = off + pos;
        if (threadIdx.x == 0) g_slot[code] = slot;
        const float4* src = (const float4*)(x + (size_t)t * H);
        float4*       dst = (float4*)(g_xg + (size_t)slot * H);
        for (int i = threadIdx.x; i < H/4; i += blockDim.x) dst[i] = src[i];
    }
}

// ---------------- FFMA2 SIMT GEMM: C(128x128) = A(128xK) * W(128xK)^T ----------------
// A stored in smem PRE-DUPLICATED as (a,a) float2 pairs -> consumer inner loop is
// 6 LDS.128 + 32 FFMA2 per kk, zero pack instructions. Accumulator pair
// (cols 2j,2j+1) = SwiGLU (glu,lin) pair. Numerics identical to plain FFMA.
template<bool SWIGLU>
__global__ __launch_bounds__(256, 2) void k_gemm(const float* __restrict__ Wbase,
                                                 const float* __restrict__ Bbase){
    int tile = blockIdx.x;
    if (tile >= g_ntiles) return;
    const int Nrows = SWIGLU ? I2 : H;
    int e     = g_tile_e[tile];
    int sbase = tile * 128;
    int n0    = blockIdx.y * 128;
    const float* A  = (SWIGLU ? g_xg : g_y) + (size_t)sbase * H;
    const float* W  = Wbase + (size_t)e * Nrows * H + (size_t)n0 * H;
    const float* bs = Bbase + (size_t)e * Nrows + n0;

    __shared__ __align__(16) float2 As2[16][130];  // [kk][row] duplicated (a,a); 130 pad -> 16B rows
    __shared__ __align__(16) float  Bs [16][132];  // [kk][ncol]

    int tid = threadIdx.x;
    int tm = (tid >> 4) << 3, tn = (tid & 15) << 3;

    // producer: 2 float4 of A and of B per thread per k-tile
    int f4a = tid*2, f4b = tid*2 + 1;
    int rowa = f4a >> 2, kqa = (f4a & 3) << 2;
    int rowb = f4b >> 2, kqb = (f4b & 3) << 2;
    const float* Apa = A + (size_t)rowa*H + kqa;
    const float* Apb = A + (size_t)rowb*H + kqb;
    const float* Wpa = W + (size_t)rowa*H + kqa;
    const float* Wpb = W + (size_t)rowb*H + kqb;

    u64t acc[8][4];
#pragma unroll
    for (int i = 0; i < 8; i++)
#pragma unroll
        for (int j = 0; j < 4; j++) acc[i][j] = 0ull;

    float4 pa0 = *(const float4*)(Apa);
    float4 pa1 = *(const float4*)(Apb);
    float4 pw0 = *(const float4*)(Wpa);
    float4 pw1 = *(const float4*)(Wpb);

    for (int kt = 0; kt < 128; kt++){
        // A duplicated pair stores (STS.64 x8), B scalar stores
        As2[kqa+0][rowa] = make_float2(pa0.x, pa0.x);
        As2[kqa+1][rowa] = make_float2(pa0.y, pa0.y);
        As2[kqa+2][rowa] = make_float2(pa0.z, pa0.z);
        As2[kqa+3][rowa] = make_float2(pa0.w, pa0.w);
        As2[kqb+0][rowb] = make_float2(pa1.x, pa1.x);
        As2[kqb+1][rowb] = make_float2(pa1.y, pa1.y);
        As2[kqb+2][rowb] = make_float2(pa1.z, pa1.z);
        As2[kqb+3][rowb] = make_float2(pa1.w, pa1.w);
        Bs[kqa+0][rowa]=pw0.x; Bs[kqa+1][rowa]=pw0.y; Bs[kqa+2][rowa]=pw0.z; Bs[kqa+3][rowa]=pw0.w;
        Bs[kqb+0][rowb]=pw1.x; Bs[kqb+1][rowb]=pw1.y; Bs[kqb+2][rowb]=pw1.z; Bs[kqb+3][rowb]=pw1.w;
        __syncthreads();
        if (kt + 1 < 128){
            int k0 = (kt + 1) * 16;
            pa0 = *(const float4*)(Apa + k0);
            pa1 = *(const float4*)(Apb + k0);
            pw0 = *(const float4*)(Wpa + k0);
            pw1 = *(const float4*)(Wpb + k0);
        }
#pragma unroll
        for (int kk = 0; kk < 16; kk++){
            const float2* Ar = &As2[kk][tm];
            ulonglong2 a01 = *(const ulonglong2*)(Ar);
            ulonglong2 a23 = *(const ulonglong2*)(Ar + 2);
            ulonglong2 a45 = *(const ulonglong2*)(Ar + 4);
            ulonglong2 a67 = *(const ulonglong2*)(Ar + 6);
            ulonglong2 bq0 = *(const ulonglong2*)&Bs[kk][tn];
            ulonglong2 bq1 = *(const ulonglong2*)&Bs[kk][tn+4];
            u64t a2[8] = { a01.x, a01.y, a23.x, a23.y, a45.x, a45.y, a67.x, a67.y };
            u64t b2[4] = { bq0.x, bq0.y, bq1.x, bq1.y };
#pragma unroll
            for (int i = 0; i < 8; i++)
#pragma unroll
                for (int j = 0; j < 4; j++) fma2(acc[i][j], a2[i], b2[j]);
        }
        __syncthreads();
    }

    if (SWIGLU){
#pragma unroll
        for (int i = 0; i < 8; i++){
            int slot = sbase + tm + i;
            float* yr = g_y + (size_t)slot * ID + ((n0 + tn) >> 1);
#pragma unroll
            for (int p = 0; p < 4; p++){
                float cg, cl;
                unpack2(acc[i][p], cg, cl);
                float glu = cg + bs[tn + 2*p];
                float lin = cl + bs[tn + 2*p + 1];
                float s = 1.f / (1.f + expf(-1.702f * glu));
                yr[p] = glu * s * (lin + 1.f);
            }
        }
    } else {
#pragma unroll
        for (int i = 0; i < 8; i++){
            int slot = sbase + tm + i;
            float* orow = g_ob + (size_t)slot * H + n0 + tn;
#pragma unroll
            for (int p = 0; p < 4; p++){
                float c0, c1;
                unpack2(acc[i][p], c0, c1);
                orow[2*p]   = c0 + bs[tn + 2*p];
                orow[2*p+1] = c1 + bs[tn + 2*p + 1];
            }
        }
    }
}

__global__ void k_comb(float* __restrict__ out){
    int gid = blockIdx.x * blockDim.x + threadIdx.x;
    if (gid >= NTOK * (H/4)) return;
    int t = gid / (H/4), c4 = gid % (H/4);
    int s0 = g_slot[2*t], s1 = g_slot[2*t + 1];
    float2 w = g_wv[t];
    float4 a = *((const float4*)(g_ob + (size_t)s0 * H) + c4);
    float4 b = *((const float4*)(g_ob + (size_t)s1 * H) + c4);
    float4 r;
    r.x = w.x*a.x + w.y*b.x; r.y = w.x*a.y + w.y*b.y;
    r.z = w.x*a.z + w.y*b.z; r.w = w.x*a.w + w.y*b.w;
    *((float4*)out + gid) = r;
}

// ---------------- launcher ----------------
extern "C" void kernel_launch(void* const* d_in, const int* in_sizes, int n_in,
                              void* d_out, int out_size){
    const float* x  = (const float*)d_in[0];
    const float* gw = (const float*)d_in[1];
    const float* gb = (const float*)d_in[2];
    const float* w1 = (const float*)d_in[3];
    const float* b1 = (const float*)d_in[4];
    const float* w2 = (const float*)d_in[5];
    const float* b2 = (const float*)d_in[6];
    float* out = (float*)d_out;

    k_init<<<1, 32>>>();
    k_gate<<<NTOK/8, 256>>>(x, gw, gb);
    k_scan<<<1, 32>>>();
    k_gather<<<dim3(NEXP, NTOK/8), 256>>>(x);
    k_gemm<true ><<<dim3(MAXTILES, I2/128), 256>>>(w1, b1);
    k_gemm<false><<<dim3(MAXTILES, H /128), 256>>>(w2, b2);
    k_comb<<<(NTOK*(H/4) + 255)/256, 256>>>(out);
}

// round 15
// speedup vs baseline: 2.3123x; 1.2078x over previous
#include <cuda_runtime.h>
#include <cstdint>

#define NEXP 8
#define NTOK 8192
#define H    2048
#define I2   4096
#define ID   2048
#define MAXTILES 136
#define PADSLOTS (MAXTILES*128)

typedef unsigned long long u64t;

// ---------------- static scratch ----------------
__device__ int    g_count[NEXP];
__device__ int    g_offset[NEXP];
__device__ int    g_ntiles;
__device__ int    g_tile_e[MAXTILES];
__device__ int    g_tok[NEXP*NTOK];
__device__ int    g_slot[NTOK*2];
__device__ float2 g_wv[NTOK];
__device__ __align__(16) float g_xg[(size_t)PADSLOTS*H];
__device__ __align__(16) float g_y [(size_t)PADSLOTS*ID];
__device__ __align__(16) float g_ob[(size_t)PADSLOTS*H];

// ---------------- f32x2 helpers ----------------
__device__ __forceinline__ u64t pack2(float lo, float hi){
    u64t r; asm("mov.b64 %0, {%1, %2};" : "=l"(r) : "f"(lo), "f"(hi)); return r;
}
__device__ __forceinline__ void unpack2(u64t v, float& lo, float& hi){
    asm("mov.b64 {%0, %1}, %2;" : "=f"(lo), "=f"(hi) : "l"(v));
}
__device__ __forceinline__ void fma2(u64t& c, u64t a, u64t b){
    asm("fma.rn.f32x2 %0, %1, %2, %0;" : "+l"(c) : "l"(a), "l"(b));
}

// ---------------- small kernels ----------------
__global__ void k_init(){ if (threadIdx.x < NEXP) g_count[threadIdx.x] = 0; }

__global__ void k_gate(const float* __restrict__ x, const float* __restrict__ gw,
                       const float* __restrict__ gb){
    int warp = (blockIdx.x * blockDim.x + threadIdx.x) >> 5;
    int lane = threadIdx.x & 31;
    if (warp >= NTOK) return;
    const float* xr = x + (size_t)warp * H;
    float acc[NEXP];
#pragma unroll
    for (int e = 0; e < NEXP; e++) acc[e] = 0.f;
    for (int i = lane; i < H; i += 32){
        float xv = xr[i];
#pragma unroll
        for (int e = 0; e < NEXP; e++) acc[e] += xv * gw[e*H + i];
    }
#pragma unroll
    for (int e = 0; e < NEXP; e++)
#pragma unroll
        for (int o = 16; o > 0; o >>= 1) acc[e] += __shfl_xor_sync(0xffffffffu, acc[e], o);
    if (lane == 0){
        float lg[NEXP];
#pragma unroll
        for (int e = 0; e < NEXP; e++) lg[e] = acc[e] + gb[e];
        int b0 = 0;
#pragma unroll
        for (int e = 1; e < NEXP; e++) if (lg[e] > lg[b0]) b0 = e;
        int b1 = -1;
#pragma unroll
        for (int e = 0; e < NEXP; e++){ if (e == b0) continue; if (b1 < 0 || lg[e] > lg[b1]) b1 = e; }
        float e1 = expf(lg[b1] - lg[b0]);
        float inv = 1.f / (1.f + e1);
        g_wv[warp] = make_float2(inv, e1 * inv);
        int p0 = atomicAdd(&g_count[b0], 1); g_tok[b0*NTOK + p0] = warp*2 + 0;
        int p1 = atomicAdd(&g_count[b1], 1); g_tok[b1*NTOK + p1] = warp*2 + 1;
    }
}

__global__ void k_scan(){
    if (threadIdx.x == 0){
        int base = 0, nt = 0;
        for (int e = 0; e < NEXP; e++){
            g_offset[e] = base;
            int t = (g_count[e] + 127) >> 7;
            for (int i = 0; i < t; i++) g_tile_e[nt++] = e;
            base += t * 128;
        }
        g_ntiles = nt;
    }
}

__global__ void k_gather(const float* __restrict__ x){
    int e = blockIdx.x, pos0 = blockIdx.y * 8, cnt = g_count[e];
    if (pos0 >= cnt) return;
    int off = g_offset[e];
    for (int r = 0; r < 8; r++){
        int pos = pos0 + r; if (pos >= cnt) break;
        int code = g_tok[e*NTOK + pos], t = code >> 1, slot = off + pos;
        if (threadIdx.x == 0) g_slot[code] = slot;
        const float4* src = (const float4*)(x + (size_t)t * H);
        float4*       dst = (float4*)(g_xg + (size_t)slot * H);
        for (int i = threadIdx.x; i < H/4; i += blockDim.x) dst[i] = src[i];
    }
}

// ---------------- FFMA SIMT GEMM, double-buffered (1 barrier per k-tile) ----------------
// C(128x128) = A(128x2048) * W(128x2048)^T. Accumulator pair (cols 2j,2j+1) =
// SwiGLU (glu,lin) pair. Numerics identical to R4 (rel_err 3.797e-7).
template<bool SWIGLU>
__global__ __launch_bounds__(256, 2) void k_gemm(const float* __restrict__ Wbase,
                                                 const float* __restrict__ Bbase){
    int tile = blockIdx.x;
    if (tile >= g_ntiles) return;
    const int Nrows = SWIGLU ? I2 : H;
    int e     = g_tile_e[tile];
    int sbase = tile * 128;
    int n0    = blockIdx.y * 128;
    const float* A  = (SWIGLU ? g_xg : g_y) + (size_t)sbase * H;
    const float* W  = Wbase + (size_t)e * Nrows * H + (size_t)n0 * H;
    const float* bs = Bbase + (size_t)e * Nrows + n0;

    __shared__ __align__(16) float As[2][16][132];
    __shared__ __align__(16) float Bs[2][16][132];
    int tid = threadIdx.x;
    int tm = (tid >> 4) << 3, tn = (tid & 15) << 3;

    int f4a = tid*2, f4b = tid*2 + 1;
    int rowa = f4a >> 2, kqa = (f4a & 3) << 2;
    int rowb = f4b >> 2, kqb = (f4b & 3) << 2;
    const float* Apa = A + (size_t)rowa*H + kqa;
    const float* Apb = A + (size_t)rowb*H + kqb;
    const float* Wpa = W + (size_t)rowa*H + kqa;
    const float* Wpb = W + (size_t)rowb*H + kqb;

    u64t acc[8][4];
#pragma unroll
    for (int i = 0; i < 8; i++)
#pragma unroll
        for (int j = 0; j < 4; j++) acc[i][j] = 0ull;

    float4 pa0 = *(const float4*)(Apa);
    float4 pa1 = *(const float4*)(Apb);
    float4 pw0 = *(const float4*)(Wpa);
    float4 pw1 = *(const float4*)(Wpb);

    for (int kt = 0; kt < 128; kt++){
        int buf = kt & 1;
        As[buf][kqa+0][rowa]=pa0.x; As[buf][kqa+1][rowa]=pa0.y; As[buf][kqa+2][rowa]=pa0.z; As[buf][kqa+3][rowa]=pa0.w;
        As[buf][kqb+0][rowb]=pa1.x; As[buf][kqb+1][rowb]=pa1.y; As[buf][kqb+2][rowb]=pa1.z; As[buf][kqb+3][rowb]=pa1.w;
        Bs[buf][kqa+0][rowa]=pw0.x; Bs[buf][kqa+1][rowa]=pw0.y; Bs[buf][kqa+2][rowa]=pw0.z; Bs[buf][kqa+3][rowa]=pw0.w;
        Bs[buf][kqb+0][rowb]=pw1.x; Bs[buf][kqb+1][rowb]=pw1.y; Bs[buf][kqb+2][rowb]=pw1.z; Bs[buf][kqb+3][rowb]=pw1.w;
        if (kt + 1 < 128){
            int k0 = (kt + 1) * 16;
            pa0 = *(const float4*)(Apa + k0);
            pa1 = *(const float4*)(Apb + k0);
            pw0 = *(const float4*)(Wpa + k0);
            pw1 = *(const float4*)(Wpb + k0);
        }
        __syncthreads();   // buf ready; prior-iter consumers of buf^1 continue below
#pragma unroll
        for (int kk = 0; kk < 16; kk++){
            float a[8];
            *(float4*)(a)   = *(const float4*)&As[buf][kk][tm];
            *(float4*)(a+4) = *(const float4*)&As[buf][kk][tm+4];
            ulonglong2 bq0 = *(const ulonglong2*)&Bs[buf][kk][tn];
            ulonglong2 bq1 = *(const ulonglong2*)&Bs[buf][kk][tn+4];
            u64t b2[4] = { bq0.x, bq0.y, bq1.x, bq1.y };
            u64t a2[8];
#pragma unroll
            for (int i = 0; i < 8; i++) a2[i] = pack2(a[i], a[i]);
#pragma unroll
            for (int i = 0; i < 8; i++)
#pragma unroll
                for (int j = 0; j < 4; j++) fma2(acc[i][j], a2[i], b2[j]);
        }
    }

    if (SWIGLU){
#pragma unroll
        for (int i = 0; i < 8; i++){
            int slot = sbase + tm + i;
            float* yr = g_y + (size_t)slot * ID + ((n0 + tn) >> 1);
#pragma unroll
            for (int p = 0; p < 4; p++){
                float cg, cl;
                unpack2(acc[i][p], cg, cl);
                float glu = cg + bs[tn + 2*p];
                float lin = cl + bs[tn + 2*p + 1];
                float s = 1.f / (1.f + expf(-1.702f * glu));
                yr[p] = glu * s * (lin + 1.f);
            }
        }
    } else {
#pragma unroll
        for (int i = 0; i < 8; i++){
            int slot = sbase + tm + i;
            float* orow = g_ob + (size_t)slot * H + n0 + tn;
#pragma unroll
            for (int p = 0; p < 4; p++){
                float c0, c1;
                unpack2(acc[i][p], c0, c1);
                orow[2*p]   = c0 + bs[tn + 2*p];
                orow[2*p+1] = c1 + bs[tn + 2*p + 1];
            }
        }
    }
}

__global__ void k_comb(float* __restrict__ out){
    int gid = blockIdx.x * blockDim.x + threadIdx.x;
    if (gid >= NTOK * (H/4)) return;
    int t = gid / (H/4), c4 = gid % (H/4);
    int s0 = g_slot[2*t], s1 = g_slot[2*t + 1];
    float2 w = g_wv[t];
    float4 a = *((const float4*)(g_ob + (size_t)s0 * H) + c4);
    float4 b = *((const float4*)(g_ob + (size_t)s1 * H) + c4);
    float4 r;
    r.x = w.x*a.x + w.y*b.x; r.y = w.x*a.y + w.y*b.y;
    r.z = w.x*a.z + w.y*b.z; r.w = w.x*a.w + w.y*b.w;
    *((float4*)out + gid) = r;
}

// ---------------- launcher ----------------
extern "C" void kernel_launch(void* const* d_in, const int* in_sizes, int n_in,
                              void* d_out, int out_size){
    const float* x  = (const float*)d_in[0];
    const float* gw = (const float*)d_in[1];
    const float* gb = (const float*)d_in[2];
    const float* w1 = (const float*)d_in[3];
    const float* b1 = (const float*)d_in[4];
    const float* w2 = (const float*)d_in[5];
    const float* b2 = (const float*)d_in[6];
    float* out = (float*)d_out;

    k_init<<<1, 32>>>();
    k_gate<<<NTOK/8, 256>>>(x, gw, gb);
    k_scan<<<1, 32>>>();
    k_gather<<<dim3(NEXP, NTOK/8), 256>>>(x);
    k_gemm<true ><<<dim3(MAXTILES, I2/128), 256>>>(w1, b1);
    k_gemm<false><<<dim3(MAXTILES, H /128), 256>>>(w2, b2);
    k_comb<<<(NTOK*(H/4) + 255)/256, 256>>>(out);
}